// round 11
// baseline (speedup 1.0000x reference)
#include <cuda_runtime.h>
#include <cuda_fp16.h>
#include <cstdint>
#include <math.h>

// GWNN on GB300 — mma.sync fp16 (m16n8k16). Conversions pipelined in halves on
// one side stream, released in dependency order; uT/hT GEMMs split by n-half
// so compute starts after only half of Winv is converted.
//   tT = w1T (x) xh         K=512  direct half epilogue
//   uT = (tT (x) Winvh)*f1  K=8192 splitK2, 2 n-halves + combine(*f1, h)
//   hT = relu(uT (x) Wh)    K=8192 splitK2, 2 n-halves + combine(relu, h)
//   sT = w2T @ hT           K=256 SIMT (h)
//   vT = (sT (x) Winvh)*f2  K=8192 splitK4 + combine(*f2, h)
//   oT = vT (x) Wh          K=8192 splitK4 (log-softmax sums float partials)

#define NR   8192
#define FIN  512
#define HID  256
#define OUTD 64

__device__ __half g_Wh   [(size_t)NR * NR];
__device__ __half g_Winvh[(size_t)NR * NR];
__device__ __half g_xh  [NR * FIN];
__device__ __half g_w1Th[HID * FIN];
__device__ __half g_tT [HID * NR];
__device__ __half g_uT [HID * NR];
__device__ __half g_hT [HID * NR];
__device__ __half g_sT [OUTD * NR];
__device__ __half g_vT [OUTD * NR];
__device__ float  g_bp [2 * HID * NR];
__device__ float  g_part[4 * OUTD * NR];

// ---------------- PTX helpers ----------------------------------------------
__device__ __forceinline__ uint32_t smem_u32(const void* p) {
    uint32_t a;
    asm("{ .reg .u64 t; cvta.to.shared.u64 t, %1; cvt.u32.u64 %0, t; }" : "=r"(a) : "l"(p));
    return a;
}
#define SWZ(x) ((x) ^ (((x) >> 3) & 0x70))

__device__ __forceinline__ void cp_async16(uint32_t dst, const void* src) {
    asm volatile("cp.async.cg.shared.global [%0], [%1], 16;" :: "r"(dst), "l"(src));
}
__device__ __forceinline__ void cp_commit() {
    asm volatile("cp.async.commit_group;" ::: "memory");
}
template <int N>
__device__ __forceinline__ void cp_wait() {
    asm volatile("cp.async.wait_group %0;" :: "n"(N) : "memory");
}
__device__ __forceinline__ void ldsm_x4(uint32_t& r0, uint32_t& r1, uint32_t& r2, uint32_t& r3,
                                        uint32_t addr) {
    asm volatile("ldmatrix.sync.aligned.m8n8.x4.shared.b16 {%0,%1,%2,%3}, [%4];"
                 : "=r"(r0), "=r"(r1), "=r"(r2), "=r"(r3) : "r"(addr));
}
__device__ __forceinline__ void mma_f16(float& d0, float& d1, float& d2, float& d3,
                                        uint32_t a0, uint32_t a1, uint32_t a2, uint32_t a3,
                                        uint32_t b0, uint32_t b1) {
    asm volatile("mma.sync.aligned.m16n8k16.row.col.f32.f16.f16.f32 "
                 "{%0,%1,%2,%3}, {%4,%5,%6,%7}, {%8,%9}, {%0,%1,%2,%3};"
                 : "+f"(d0), "+f"(d1), "+f"(d2), "+f"(d3)
                 : "r"(a0), "r"(a1), "r"(a2), "r"(a3), "r"(b0), "r"(b1));
}

// ---------------- fp16 mma GEMM ---------------------------------------------
// D[BM, BN] of A[M,K]*B[N,K]^T; A,B fp16 K-major (stride Kfull halves).
// n0 = n_base + blockIdx.x*BN (n-half launches). Split-K via gridDim.z.
// OUTH=0: float partials (C += z*cstride). OUTH=1: __half direct.
template <int MT, int NT, int S, int OUTH>
__global__ __launch_bounds__(256, 2)
void mm_f16_kernel(const __half* __restrict__ A, const __half* __restrict__ B,
                   void* __restrict__ Cv, int Kfull, int Kchunk, size_t cstride,
                   int n_base)
{
    constexpr int BM = MT * 32, BN = NT * 32;
    constexpr int NP = NT / 2;
    constexpr int AI = BM / 32;
    constexpr int BI = BN / 32;
    constexpr int A_BYTES = BM * 128;
    constexpr int B_BYTES = BN * 128;
    constexpr int STAGE   = A_BYTES + B_BYTES;

    extern __shared__ char smem[];
    const uint32_t sb = smem_u32(smem);
    const int tid    = threadIdx.x;
    const int wid    = tid >> 5;
    const int lane   = tid & 31;
    const int warp_m = wid & 1;
    const int warp_n = wid >> 1;

    const int m0 = blockIdx.y * BM;
    const int n0 = n_base + blockIdx.x * BN;
    const int k0 = blockIdx.z * Kchunk;

    const __half* Ab = A + (size_t)m0 * Kfull + k0;
    const __half* Bb = B + (size_t)n0 * Kfull + k0;
    const int KT = Kchunk >> 6;

    const int lr = tid >> 3;
    const int lc = tid & 7;
    const __half* aP0 = Ab + (size_t)lr * Kfull + lc * 8;
    const __half* bP0 = Bb + (size_t)lr * Kfull + lc * 8;
    const size_t rstep = (size_t)32 * Kfull;
    const uint32_t d0 = SWZ(lr * 128 + lc * 16);

    const int a_row  = warp_m * (MT * 16) + (lane & 15);
    const int a_byte = (lane >> 4) << 4;
    const int b_row  = warp_n * (NT * 8) + ((lane >> 4) << 3) + (lane & 7);
    const int b_byte = (lane & 8) << 1;

    float acc[MT][NT][4];
    #pragma unroll
    for (int mt = 0; mt < MT; ++mt)
        #pragma unroll
        for (int nt = 0; nt < NT; ++nt)
            #pragma unroll
            for (int q = 0; q < 4; ++q) acc[mt][nt][q] = 0.0f;

    auto load_stage = [&](int stg) {
        const uint32_t as = sb + (stg % S) * STAGE;
        const uint32_t bs = as + A_BYTES;
        const int koff = stg << 6;
        #pragma unroll
        for (int it = 0; it < AI; ++it)
            cp_async16(as + d0 + it * 4096, aP0 + it * rstep + koff);
        #pragma unroll
        for (int it = 0; it < BI; ++it)
            cp_async16(bs + d0 + it * 4096, bP0 + it * rstep + koff);
    };

    #pragma unroll
    for (int p = 0; p < S - 1; ++p) {
        if (p < KT) load_stage(p);
        cp_commit();
    }

    for (int i = 0; i < KT; ++i) {
        cp_wait<S - 2>();
        __syncthreads();
        if (i + S - 1 < KT) load_stage(i + S - 1);
        cp_commit();

        const uint32_t as = sb + (i % S) * STAGE;
        const uint32_t bs = as + A_BYTES;

        #pragma unroll
        for (int ks = 0; ks < 4; ++ks) {
            uint32_t af[MT][4], bf[NP][4];
            #pragma unroll
            for (int mt = 0; mt < MT; ++mt)
                ldsm_x4(af[mt][0], af[mt][1], af[mt][2], af[mt][3],
                        as + SWZ((a_row + mt * 16) * 128 + ks * 32 + a_byte));
            #pragma unroll
            for (int np = 0; np < NP; ++np)
                ldsm_x4(bf[np][0], bf[np][1], bf[np][2], bf[np][3],
                        bs + SWZ((b_row + np * 16) * 128 + ks * 32 + b_byte));
            #pragma unroll
            for (int mt = 0; mt < MT; ++mt)
                #pragma unroll
                for (int nt = 0; nt < NT; ++nt)
                    mma_f16(acc[mt][nt][0], acc[mt][nt][1], acc[mt][nt][2], acc[mt][nt][3],
                            af[mt][0], af[mt][1], af[mt][2], af[mt][3],
                            bf[nt >> 1][(nt & 1) * 2], bf[nt >> 1][(nt & 1) * 2 + 1]);
        }
    }

    const int er = m0 + warp_m * (MT * 16) + (lane >> 2);
    const int ec = n0 + warp_n * (NT * 8) + (lane & 3) * 2;
    if (OUTH) {
        __half* C = (__half*)Cv;
        #pragma unroll
        for (int mt = 0; mt < MT; ++mt)
            #pragma unroll
            for (int nt = 0; nt < NT; ++nt) {
                const int row = er + mt * 16;
                const int col = ec + nt * 8;
                *(__half2*)&C[(size_t)row * NR + col] =
                    __floats2half2_rn(acc[mt][nt][0], acc[mt][nt][1]);
                *(__half2*)&C[(size_t)(row + 8) * NR + col] =
                    __floats2half2_rn(acc[mt][nt][2], acc[mt][nt][3]);
            }
    } else {
        float* C = (float*)Cv + (size_t)blockIdx.z * cstride;
        #pragma unroll
        for (int mt = 0; mt < MT; ++mt)
            #pragma unroll
            for (int nt = 0; nt < NT; ++nt) {
                const int row = er + mt * 16;
                const int col = ec + nt * 8;
                *(float2*)&C[(size_t)row * NR + col] =
                    make_float2(acc[mt][nt][0], acc[mt][nt][1]);
                *(float2*)&C[(size_t)(row + 8) * NR + col] =
                    make_float2(acc[mt][nt][2], acc[mt][nt][3]);
            }
    }
}

// ---------------- small kernels ---------------------------------------------
__global__ __launch_bounds__(256)
void cvt_f16_kernel(const float* __restrict__ in, __half* __restrict__ out, size_t n)
{
    const size_t i = ((size_t)blockIdx.x * 256 + threadIdx.x) * 8;
    if (i >= n) return;
    float4 a = *(const float4*)(in + i);
    float4 b = *(const float4*)(in + i + 4);
    __half2 h0 = __floats2half2_rn(a.x, a.y);
    __half2 h1 = __floats2half2_rn(a.z, a.w);
    __half2 h2 = __floats2half2_rn(b.x, b.y);
    __half2 h3 = __floats2half2_rn(b.z, b.w);
    uint4 o;
    o.x = *(uint32_t*)&h0; o.y = *(uint32_t*)&h1;
    o.z = *(uint32_t*)&h2; o.w = *(uint32_t*)&h3;
    *(uint4*)(out + i) = o;
}

__global__ __launch_bounds__(256)
void transpose_h_kernel(const float* __restrict__ in, __half* __restrict__ out,
                        int R, int C)
{
    __shared__ float tile[32][33];
    const int c0 = blockIdx.x * 32;
    const int r0 = blockIdx.y * 32;
    const int tx = threadIdx.x, ty = threadIdx.y;
    #pragma unroll
    for (int i = 0; i < 32; i += 8)
        tile[ty + i][tx] = in[(size_t)(r0 + ty + i) * C + c0 + tx];
    __syncthreads();
    #pragma unroll
    for (int i = 0; i < 32; i += 8)
        out[(size_t)(c0 + ty + i) * R + r0 + tx] = __float2half_rn(tile[tx][ty + i]);
}

// big split-K combine -> half: MODE 0 (P0+P1)*f[col]; 1 relu(P0+P1)
template <int MODE>
__global__ __launch_bounds__(256)
void combine_big_kernel(const float* __restrict__ P, const float* __restrict__ f,
                        __half* __restrict__ out)
{
    constexpr size_t CH = (size_t)HID * NR;
    const size_t idx = (size_t)blockIdx.x * 256 + threadIdx.x;
    float v = P[idx] + P[idx + CH];
    if (MODE == 0) v *= f[(int)(idx & (NR - 1))];
    if (MODE == 1) v = fmaxf(v, 0.0f);
    out[idx] = __float2half_rn(v);
}

// sT[j,n] = half( sum_f w2[f,j] * hT[f,n] )   (64 x 8192, K=256) — SIMT
__global__ __launch_bounds__(256)
void gemm_small_kernel(const float* __restrict__ w2, const __half* __restrict__ hT,
                       __half* __restrict__ sT)
{
    __shared__ float As[32][64];
    __shared__ float Bs[32][136];
    const int tid = threadIdx.x;
    const int n0 = blockIdx.x * 128;
    const int tj = (tid >> 4) * 4;
    const int tn = (tid & 15) * 8;

    float acc[4][8];
    #pragma unroll
    for (int i = 0; i < 4; ++i)
        #pragma unroll
        for (int j = 0; j < 8; ++j) acc[i][j] = 0.0f;

    for (int f0 = 0; f0 < HID; f0 += 32) {
        #pragma unroll
        for (int it = 0; it < 8; ++it) {
            int idx = tid + it * 256;
            As[idx >> 6][idx & 63] = w2[(size_t)(f0 + (idx >> 6)) * OUTD + (idx & 63)];
        }
        #pragma unroll
        for (int it = 0; it < 2; ++it) {
            int idx = tid + it * 256;
            int f = idx >> 4, n = (idx & 15) * 8;
            uint4 raw = *(const uint4*)(hT + (size_t)(f0 + f) * NR + n0 + n);
            const __half2* hp = (const __half2*)&raw;
            #pragma unroll
            for (int q = 0; q < 4; ++q) {
                float2 fv = __half22float2(hp[q]);
                Bs[f][n + q * 2]     = fv.x;
                Bs[f][n + q * 2 + 1] = fv.y;
            }
        }
        __syncthreads();
        #pragma unroll
        for (int kk = 0; kk < 32; ++kk) {
            float a[4], b[8];
            #pragma unroll
            for (int i = 0; i < 4; ++i) a[i] = As[kk][tj + i];
            #pragma unroll
            for (int j = 0; j < 8; ++j) b[j] = Bs[kk][tn + j];
            #pragma unroll
            for (int i = 0; i < 4; ++i)
                #pragma unroll
                for (int j = 0; j < 8; ++j) acc[i][j] = fmaf(a[i], b[j], acc[i][j]);
        }
        __syncthreads();
    }
    #pragma unroll
    for (int i = 0; i < 4; ++i) {
        __half* row = sT + (size_t)(tj + i) * NR + n0 + tn;
        #pragma unroll
        for (int j = 0; j < 8; ++j) row[j] = __float2half_rn(acc[i][j]);
    }
}

// vT = half( (sum_z part_z) * f2[col] )
__global__ __launch_bounds__(256)
void combine_vT_kernel(const float* __restrict__ P, const float* __restrict__ f2,
                       __half* __restrict__ vT)
{
    constexpr size_t CH = (size_t)OUTD * NR;
    const size_t idx = (size_t)blockIdx.x * 256 + threadIdx.x;
    const int n = (int)(idx & (NR - 1));
    float v = P[idx] + P[idx + CH] + P[idx + 2 * CH] + P[idx + 3 * CH];
    vT[idx] = __float2half_rn(v * f2[n]);
}

// out[m, j] = (sum_z P_z[j, m]) - logsumexp_j
__global__ __launch_bounds__(256)
void logsoftmax_part_kernel(const float* __restrict__ P, float* __restrict__ out)
{
    constexpr size_t CH = (size_t)OUTD * NR;
    const int m = blockIdx.x * blockDim.x + threadIdx.x;
    if (m >= NR) return;
    float v[OUTD];
    float mx = -1e30f;
    #pragma unroll
    for (int j = 0; j < OUTD; ++j) {
        const size_t base = (size_t)j * NR + m;
        v[j] = P[base] + P[base + CH] + P[base + 2 * CH] + P[base + 3 * CH];
        mx = fmaxf(mx, v[j]);
    }
    float s = 0.0f;
    #pragma unroll
    for (int j = 0; j < OUTD; ++j) s += expf(v[j] - mx);
    const float lse = mx + logf(s);
    #pragma unroll
    for (int j = 0; j < OUTD; ++j) out[(size_t)m * OUTD + j] = v[j] - lse;
}

// ---------------- kernel_launch ---------------------------------------------
extern "C" void kernel_launch(void* const* d_in, const int* in_sizes, int n_in,
                              void* d_out, int out_size)
{
    (void)in_sizes; (void)n_in; (void)out_size;
    const float* x    = (const float*)d_in[0];
    const float* W    = (const float*)d_in[1];
    const float* Winv = (const float*)d_in[2];
    const float* w1   = (const float*)d_in[3];
    const float* f1   = (const float*)d_in[4];
    const float* w2   = (const float*)d_in[5];
    const float* f2   = (const float*)d_in[6];
    float* out = (float*)d_out;

    __half *Wh, *Winvh, *xh, *w1Th, *tT, *uT, *hT, *sT, *vT;
    float *bp, *part;
    cudaGetSymbolAddress((void**)&Wh,    g_Wh);
    cudaGetSymbolAddress((void**)&Winvh, g_Winvh);
    cudaGetSymbolAddress((void**)&xh,    g_xh);
    cudaGetSymbolAddress((void**)&w1Th,  g_w1Th);
    cudaGetSymbolAddress((void**)&tT,    g_tT);
    cudaGetSymbolAddress((void**)&uT,    g_uT);
    cudaGetSymbolAddress((void**)&hT,    g_hT);
    cudaGetSymbolAddress((void**)&sT,    g_sT);
    cudaGetSymbolAddress((void**)&vT,    g_vT);
    cudaGetSymbolAddress((void**)&bp,    g_bp);
    cudaGetSymbolAddress((void**)&part,  g_part);

    // side stream + events (created once, on the uncaptured correctness call)
    static cudaStream_t s1 = nullptr;
    static cudaEvent_t  eFork = nullptr, eW1 = nullptr, eW2 = nullptr,
                        eV1 = nullptr, eV2 = nullptr;
    if (s1 == nullptr) {
        cudaStreamCreateWithFlags(&s1, cudaStreamNonBlocking);
        cudaEventCreateWithFlags(&eFork, cudaEventDisableTiming);
        cudaEventCreateWithFlags(&eW1, cudaEventDisableTiming);
        cudaEventCreateWithFlags(&eW2, cudaEventDisableTiming);
        cudaEventCreateWithFlags(&eV1, cudaEventDisableTiming);
        cudaEventCreateWithFlags(&eV2, cudaEventDisableTiming);
    }

    constexpr int SMEM_BIG = 3 * (128 + 128) * 128;   // 98304
    constexpr int SMEM_SK  = 4 * (64 + 128) * 128;    // 98304
    cudaFuncSetAttribute(mm_f16_kernel<4, 4, 3, 0>, cudaFuncAttributeMaxDynamicSharedMemorySize, SMEM_BIG);
    cudaFuncSetAttribute(mm_f16_kernel<4, 4, 3, 1>, cudaFuncAttributeMaxDynamicSharedMemorySize, SMEM_BIG);
    cudaFuncSetAttribute(mm_f16_kernel<2, 4, 4, 0>, cudaFuncAttributeMaxDynamicSharedMemorySize, SMEM_SK);

    constexpr size_t BIG_CH = (size_t)HID * NR;
    constexpr size_t SK_CH  = (size_t)OUTD * NR;
    constexpr size_t NN  = (size_t)NR * NR;
    constexpr size_t HN  = NN / 2;
    const int cvtHalfGrid = (int)(HN / (256 * 8));

    // side stream: conversions SEQUENTIAL in dependency-release order.
    cudaEventRecord(eFork, 0);
    cudaStreamWaitEvent(s1, eFork, 0);
    cvt_f16_kernel<<<cvtHalfGrid, 256, 0, s1>>>(Winv,      Winvh,      HN);
    cudaEventRecord(eW1, s1);
    cvt_f16_kernel<<<cvtHalfGrid, 256, 0, s1>>>(Winv + HN, Winvh + HN, HN);
    cudaEventRecord(eW2, s1);
    cvt_f16_kernel<<<cvtHalfGrid, 256, 0, s1>>>(W,         Wh,         HN);
    cudaEventRecord(eV1, s1);
    cvt_f16_kernel<<<cvtHalfGrid, 256, 0, s1>>>(W + HN,    Wh + HN,    HN);
    cudaEventRecord(eV2, s1);

    // main stream: x/w1 prep + tT GEMM concurrent with Winv conversion
    cvt_f16_kernel<<<(NR * FIN) / (256 * 8), 256>>>(x, xh, (size_t)NR * FIN);
    transpose_h_kernel<<<dim3(HID / 32, FIN / 32), dim3(32, 8)>>>(w1, w1Th, FIN, HID);
    mm_f16_kernel<4, 4, 3, 1><<<dim3(NR / 128, HID / 128, 1), 256, SMEM_BIG>>>(
        w1Th, xh, tT, FIN, FIN, 0, 0);

    // uT: two n-halves, each gated on its Winv half (splitK2 each)
    cudaStreamWaitEvent(0, eW1, 0);
    mm_f16_kernel<4, 4, 3, 0><<<dim3(NR / 256, HID / 128, 2), 256, SMEM_BIG>>>(
        tT, Winvh, bp, NR, NR / 2, BIG_CH, 0);
    cudaStreamWaitEvent(0, eW2, 0);
    mm_f16_kernel<4, 4, 3, 0><<<dim3(NR / 256, HID / 128, 2), 256, SMEM_BIG>>>(
        tT, Winvh, bp, NR, NR / 2, BIG_CH, NR / 2);
    combine_big_kernel<0><<<(int)(BIG_CH / 256), 256>>>(bp, f1, uT);

    // hT: two n-halves, each gated on its W half
    cudaStreamWaitEvent(0, eV1, 0);
    mm_f16_kernel<4, 4, 3, 0><<<dim3(NR / 256, HID / 128, 2), 256, SMEM_BIG>>>(
        uT, Wh, bp, NR, NR / 2, BIG_CH, 0);
    cudaStreamWaitEvent(0, eV2, 0);
    mm_f16_kernel<4, 4, 3, 0><<<dim3(NR / 256, HID / 128, 2), 256, SMEM_BIG>>>(
        uT, Wh, bp, NR, NR / 2, BIG_CH, NR / 2);
    combine_big_kernel<1><<<(int)(BIG_CH / 256), 256>>>(bp, nullptr, hT);

    // layer 2
    gemm_small_kernel<<<NR / 128, 256>>>(w2, hT, sT);
    mm_f16_kernel<2, 4, 4, 0><<<dim3(NR / 128, 1, 4), 256, SMEM_SK>>>(
        sT, Winvh, part, NR, NR / 4, SK_CH, 0);
    combine_vT_kernel<<<(int)(SK_CH / 256), 256>>>(part, f2, vT);
    mm_f16_kernel<2, 4, 4, 0><<<dim3(NR / 128, 1, 4), 256, SMEM_SK>>>(
        vT, Wh, part, NR, NR / 4, SK_CH, 0);
    logsoftmax_part_kernel<<<NR / 256, 256>>>(part, out);
}

// round 12
// speedup vs baseline: 1.0466x; 1.0466x over previous
#include <cuda_runtime.h>
#include <cuda_fp16.h>
#include <cstdint>
#include <math.h>

// GWNN on GB300 — mma.sync fp16 (m16n8k16). R10 structure; conversions now
// SEQUENTIAL on the side stream in dependency order (Winv first -> uT gate
// releases at ~55us instead of ~110us; W converts under the uT GEMM).
//   tT = w1T (x) xh         K=512  direct half epilogue
//   uT = (tT (x) Winvh)*f1  K=8192 splitK2 + combine(*f1, h)
//   hT = relu(uT (x) Wh)    K=8192 splitK2 + combine(relu, h)
//   sT = w2T @ hT           K=256 SIMT (h)
//   vT = (sT (x) Winvh)*f2  K=8192 splitK4 + combine(*f2, h)
//   oT = vT (x) Wh          K=8192 splitK4 (log-softmax sums float partials)

#define NR   8192
#define FIN  512
#define HID  256
#define OUTD 64

__device__ __half g_Wh   [(size_t)NR * NR];
__device__ __half g_Winvh[(size_t)NR * NR];
__device__ __half g_xh  [NR * FIN];
__device__ __half g_w1Th[HID * FIN];
__device__ __half g_tT [HID * NR];
__device__ __half g_uT [HID * NR];
__device__ __half g_hT [HID * NR];
__device__ __half g_sT [OUTD * NR];
__device__ __half g_vT [OUTD * NR];
__device__ float  g_bp [2 * HID * NR];
__device__ float  g_part[4 * OUTD * NR];

// ---------------- PTX helpers ----------------------------------------------
__device__ __forceinline__ uint32_t smem_u32(const void* p) {
    uint32_t a;
    asm("{ .reg .u64 t; cvta.to.shared.u64 t, %1; cvt.u32.u64 %0, t; }" : "=r"(a) : "l"(p));
    return a;
}
#define SWZ(x) ((x) ^ (((x) >> 3) & 0x70))

__device__ __forceinline__ void cp_async16(uint32_t dst, const void* src) {
    asm volatile("cp.async.cg.shared.global [%0], [%1], 16;" :: "r"(dst), "l"(src));
}
__device__ __forceinline__ void cp_commit() {
    asm volatile("cp.async.commit_group;" ::: "memory");
}
template <int N>
__device__ __forceinline__ void cp_wait() {
    asm volatile("cp.async.wait_group %0;" :: "n"(N) : "memory");
}
__device__ __forceinline__ void ldsm_x4(uint32_t& r0, uint32_t& r1, uint32_t& r2, uint32_t& r3,
                                        uint32_t addr) {
    asm volatile("ldmatrix.sync.aligned.m8n8.x4.shared.b16 {%0,%1,%2,%3}, [%4];"
                 : "=r"(r0), "=r"(r1), "=r"(r2), "=r"(r3) : "r"(addr));
}
__device__ __forceinline__ void mma_f16(float& d0, float& d1, float& d2, float& d3,
                                        uint32_t a0, uint32_t a1, uint32_t a2, uint32_t a3,
                                        uint32_t b0, uint32_t b1) {
    asm volatile("mma.sync.aligned.m16n8k16.row.col.f32.f16.f16.f32 "
                 "{%0,%1,%2,%3}, {%4,%5,%6,%7}, {%8,%9}, {%0,%1,%2,%3};"
                 : "+f"(d0), "+f"(d1), "+f"(d2), "+f"(d3)
                 : "r"(a0), "r"(a1), "r"(a2), "r"(a3), "r"(b0), "r"(b1));
}

// ---------------- fp16 mma GEMM ---------------------------------------------
// D[BM, BN] of A[M,K]*B[N,K]^T; A,B fp16 K-major (stride Kfull halves).
// OUTH=0: float partials (C += z*cstride, split-K). OUTH=1: __half direct.
template <int MT, int NT, int S, int OUTH>
__global__ __launch_bounds__(256, 2)
void mm_f16_kernel(const __half* __restrict__ A, const __half* __restrict__ B,
                   void* __restrict__ Cv, int Kfull, int Kchunk, size_t cstride)
{
    constexpr int BM = MT * 32, BN = NT * 32;
    constexpr int NP = NT / 2;
    constexpr int AI = BM / 32;
    constexpr int BI = BN / 32;
    constexpr int A_BYTES = BM * 128;
    constexpr int B_BYTES = BN * 128;
    constexpr int STAGE   = A_BYTES + B_BYTES;

    extern __shared__ char smem[];
    const uint32_t sb = smem_u32(smem);
    const int tid    = threadIdx.x;
    const int wid    = tid >> 5;
    const int lane   = tid & 31;
    const int warp_m = wid & 1;
    const int warp_n = wid >> 1;

    const int m0 = blockIdx.y * BM;
    const int n0 = blockIdx.x * BN;
    const int k0 = blockIdx.z * Kchunk;

    const __half* Ab = A + (size_t)m0 * Kfull + k0;
    const __half* Bb = B + (size_t)n0 * Kfull + k0;
    const int KT = Kchunk >> 6;

    const int lr = tid >> 3;
    const int lc = tid & 7;
    const __half* aP0 = Ab + (size_t)lr * Kfull + lc * 8;
    const __half* bP0 = Bb + (size_t)lr * Kfull + lc * 8;
    const size_t rstep = (size_t)32 * Kfull;
    const uint32_t d0 = SWZ(lr * 128 + lc * 16);

    const int a_row  = warp_m * (MT * 16) + (lane & 15);
    const int a_byte = (lane >> 4) << 4;
    const int b_row  = warp_n * (NT * 8) + ((lane >> 4) << 3) + (lane & 7);
    const int b_byte = (lane & 8) << 1;

    float acc[MT][NT][4];
    #pragma unroll
    for (int mt = 0; mt < MT; ++mt)
        #pragma unroll
        for (int nt = 0; nt < NT; ++nt)
            #pragma unroll
            for (int q = 0; q < 4; ++q) acc[mt][nt][q] = 0.0f;

    auto load_stage = [&](int stg) {
        const uint32_t as = sb + (stg % S) * STAGE;
        const uint32_t bs = as + A_BYTES;
        const int koff = stg << 6;
        #pragma unroll
        for (int it = 0; it < AI; ++it)
            cp_async16(as + d0 + it * 4096, aP0 + it * rstep + koff);
        #pragma unroll
        for (int it = 0; it < BI; ++it)
            cp_async16(bs + d0 + it * 4096, bP0 + it * rstep + koff);
    };

    #pragma unroll
    for (int p = 0; p < S - 1; ++p) {
        if (p < KT) load_stage(p);
        cp_commit();
    }

    for (int i = 0; i < KT; ++i) {
        cp_wait<S - 2>();
        __syncthreads();
        if (i + S - 1 < KT) load_stage(i + S - 1);
        cp_commit();

        const uint32_t as = sb + (i % S) * STAGE;
        const uint32_t bs = as + A_BYTES;

        #pragma unroll
        for (int ks = 0; ks < 4; ++ks) {
            uint32_t af[MT][4], bf[NP][4];
            #pragma unroll
            for (int mt = 0; mt < MT; ++mt)
                ldsm_x4(af[mt][0], af[mt][1], af[mt][2], af[mt][3],
                        as + SWZ((a_row + mt * 16) * 128 + ks * 32 + a_byte));
            #pragma unroll
            for (int np = 0; np < NP; ++np)
                ldsm_x4(bf[np][0], bf[np][1], bf[np][2], bf[np][3],
                        bs + SWZ((b_row + np * 16) * 128 + ks * 32 + b_byte));
            #pragma unroll
            for (int mt = 0; mt < MT; ++mt)
                #pragma unroll
                for (int nt = 0; nt < NT; ++nt)
                    mma_f16(acc[mt][nt][0], acc[mt][nt][1], acc[mt][nt][2], acc[mt][nt][3],
                            af[mt][0], af[mt][1], af[mt][2], af[mt][3],
                            bf[nt >> 1][(nt & 1) * 2], bf[nt >> 1][(nt & 1) * 2 + 1]);
        }
    }

    const int er = m0 + warp_m * (MT * 16) + (lane >> 2);
    const int ec = n0 + warp_n * (NT * 8) + (lane & 3) * 2;
    if (OUTH) {
        __half* C = (__half*)Cv;
        #pragma unroll
        for (int mt = 0; mt < MT; ++mt)
            #pragma unroll
            for (int nt = 0; nt < NT; ++nt) {
                const int row = er + mt * 16;
                const int col = ec + nt * 8;
                *(__half2*)&C[(size_t)row * NR + col] =
                    __floats2half2_rn(acc[mt][nt][0], acc[mt][nt][1]);
                *(__half2*)&C[(size_t)(row + 8) * NR + col] =
                    __floats2half2_rn(acc[mt][nt][2], acc[mt][nt][3]);
            }
    } else {
        float* C = (float*)Cv + (size_t)blockIdx.z * cstride;
        #pragma unroll
        for (int mt = 0; mt < MT; ++mt)
            #pragma unroll
            for (int nt = 0; nt < NT; ++nt) {
                const int row = er + mt * 16;
                const int col = ec + nt * 8;
                *(float2*)&C[(size_t)row * NR + col] =
                    make_float2(acc[mt][nt][0], acc[mt][nt][1]);
                *(float2*)&C[(size_t)(row + 8) * NR + col] =
                    make_float2(acc[mt][nt][2], acc[mt][nt][3]);
            }
    }
}

// ---------------- small kernels ---------------------------------------------
__global__ __launch_bounds__(256)
void cvt_f16_kernel(const float* __restrict__ in, __half* __restrict__ out, size_t n)
{
    const size_t i = ((size_t)blockIdx.x * 256 + threadIdx.x) * 8;
    if (i >= n) return;
    float4 a = *(const float4*)(in + i);
    float4 b = *(const float4*)(in + i + 4);
    __half2 h0 = __floats2half2_rn(a.x, a.y);
    __half2 h1 = __floats2half2_rn(a.z, a.w);
    __half2 h2 = __floats2half2_rn(b.x, b.y);
    __half2 h3 = __floats2half2_rn(b.z, b.w);
    uint4 o;
    o.x = *(uint32_t*)&h0; o.y = *(uint32_t*)&h1;
    o.z = *(uint32_t*)&h2; o.w = *(uint32_t*)&h3;
    *(uint4*)(out + i) = o;
}

__global__ __launch_bounds__(256)
void transpose_h_kernel(const float* __restrict__ in, __half* __restrict__ out,
                        int R, int C)
{
    __shared__ float tile[32][33];
    const int c0 = blockIdx.x * 32;
    const int r0 = blockIdx.y * 32;
    const int tx = threadIdx.x, ty = threadIdx.y;
    #pragma unroll
    for (int i = 0; i < 32; i += 8)
        tile[ty + i][tx] = in[(size_t)(r0 + ty + i) * C + c0 + tx];
    __syncthreads();
    #pragma unroll
    for (int i = 0; i < 32; i += 8)
        out[(size_t)(c0 + ty + i) * R + r0 + tx] = __float2half_rn(tile[tx][ty + i]);
}

// big split-K combine -> half: MODE 0 (P0+P1)*f[col]; 1 relu(P0+P1)
template <int MODE>
__global__ __launch_bounds__(256)
void combine_big_kernel(const float* __restrict__ P, const float* __restrict__ f,
                        __half* __restrict__ out)
{
    constexpr size_t CH = (size_t)HID * NR;
    const size_t idx = (size_t)blockIdx.x * 256 + threadIdx.x;
    float v = P[idx] + P[idx + CH];
    if (MODE == 0) v *= f[(int)(idx & (NR - 1))];
    if (MODE == 1) v = fmaxf(v, 0.0f);
    out[idx] = __float2half_rn(v);
}

// sT[j,n] = half( sum_f w2[f,j] * hT[f,n] )   (64 x 8192, K=256) — SIMT
__global__ __launch_bounds__(256)
void gemm_small_kernel(const float* __restrict__ w2, const __half* __restrict__ hT,
                       __half* __restrict__ sT)
{
    __shared__ float As[32][64];
    __shared__ float Bs[32][136];
    const int tid = threadIdx.x;
    const int n0 = blockIdx.x * 128;
    const int tj = (tid >> 4) * 4;
    const int tn = (tid & 15) * 8;

    float acc[4][8];
    #pragma unroll
    for (int i = 0; i < 4; ++i)
        #pragma unroll
        for (int j = 0; j < 8; ++j) acc[i][j] = 0.0f;

    for (int f0 = 0; f0 < HID; f0 += 32) {
        #pragma unroll
        for (int it = 0; it < 8; ++it) {
            int idx = tid + it * 256;
            As[idx >> 6][idx & 63] = w2[(size_t)(f0 + (idx >> 6)) * OUTD + (idx & 63)];
        }
        #pragma unroll
        for (int it = 0; it < 2; ++it) {
            int idx = tid + it * 256;
            int f = idx >> 4, n = (idx & 15) * 8;
            uint4 raw = *(const uint4*)(hT + (size_t)(f0 + f) * NR + n0 + n);
            const __half2* hp = (const __half2*)&raw;
            #pragma unroll
            for (int q = 0; q < 4; ++q) {
                float2 fv = __half22float2(hp[q]);
                Bs[f][n + q * 2]     = fv.x;
                Bs[f][n + q * 2 + 1] = fv.y;
            }
        }
        __syncthreads();
        #pragma unroll
        for (int kk = 0; kk < 32; ++kk) {
            float a[4], b[8];
            #pragma unroll
            for (int i = 0; i < 4; ++i) a[i] = As[kk][tj + i];
            #pragma unroll
            for (int j = 0; j < 8; ++j) b[j] = Bs[kk][tn + j];
            #pragma unroll
            for (int i = 0; i < 4; ++i)
                #pragma unroll
                for (int j = 0; j < 8; ++j) acc[i][j] = fmaf(a[i], b[j], acc[i][j]);
        }
        __syncthreads();
    }
    #pragma unroll
    for (int i = 0; i < 4; ++i) {
        __half* row = sT + (size_t)(tj + i) * NR + n0 + tn;
        #pragma unroll
        for (int j = 0; j < 8; ++j) row[j] = __float2half_rn(acc[i][j]);
    }
}

// vT = half( (sum_z part_z) * f2[col] )
__global__ __launch_bounds__(256)
void combine_vT_kernel(const float* __restrict__ P, const float* __restrict__ f2,
                       __half* __restrict__ vT)
{
    constexpr size_t CH = (size_t)OUTD * NR;
    const size_t idx = (size_t)blockIdx.x * 256 + threadIdx.x;
    const int n = (int)(idx & (NR - 1));
    float v = P[idx] + P[idx + CH] + P[idx + 2 * CH] + P[idx + 3 * CH];
    vT[idx] = __float2half_rn(v * f2[n]);
}

// out[m, j] = (sum_z P_z[j, m]) - logsumexp_j
__global__ __launch_bounds__(256)
void logsoftmax_part_kernel(const float* __restrict__ P, float* __restrict__ out)
{
    constexpr size_t CH = (size_t)OUTD * NR;
    const int m = blockIdx.x * blockDim.x + threadIdx.x;
    if (m >= NR) return;
    float v[OUTD];
    float mx = -1e30f;
    #pragma unroll
    for (int j = 0; j < OUTD; ++j) {
        const size_t base = (size_t)j * NR + m;
        v[j] = P[base] + P[base + CH] + P[base + 2 * CH] + P[base + 3 * CH];
        mx = fmaxf(mx, v[j]);
    }
    float s = 0.0f;
    #pragma unroll
    for (int j = 0; j < OUTD; ++j) s += expf(v[j] - mx);
    const float lse = mx + logf(s);
    #pragma unroll
    for (int j = 0; j < OUTD; ++j) out[(size_t)m * OUTD + j] = v[j] - lse;
}

// ---------------- kernel_launch ---------------------------------------------
extern "C" void kernel_launch(void* const* d_in, const int* in_sizes, int n_in,
                              void* d_out, int out_size)
{
    (void)in_sizes; (void)n_in; (void)out_size;
    const float* x    = (const float*)d_in[0];
    const float* W    = (const float*)d_in[1];
    const float* Winv = (const float*)d_in[2];
    const float* w1   = (const float*)d_in[3];
    const float* f1   = (const float*)d_in[4];
    const float* w2   = (const float*)d_in[5];
    const float* f2   = (const float*)d_in[6];
    float* out = (float*)d_out;

    __half *Wh, *Winvh, *xh, *w1Th, *tT, *uT, *hT, *sT, *vT;
    float *bp, *part;
    cudaGetSymbolAddress((void**)&Wh,    g_Wh);
    cudaGetSymbolAddress((void**)&Winvh, g_Winvh);
    cudaGetSymbolAddress((void**)&xh,    g_xh);
    cudaGetSymbolAddress((void**)&w1Th,  g_w1Th);
    cudaGetSymbolAddress((void**)&tT,    g_tT);
    cudaGetSymbolAddress((void**)&uT,    g_uT);
    cudaGetSymbolAddress((void**)&hT,    g_hT);
    cudaGetSymbolAddress((void**)&sT,    g_sT);
    cudaGetSymbolAddress((void**)&vT,    g_vT);
    cudaGetSymbolAddress((void**)&bp,    g_bp);
    cudaGetSymbolAddress((void**)&part,  g_part);

    // side stream + events, created once on the (uncaptured) correctness call
    static cudaStream_t s1 = nullptr;
    static cudaEvent_t  eFork = nullptr, e1 = nullptr, e2 = nullptr;
    if (s1 == nullptr) {
        cudaStreamCreateWithFlags(&s1, cudaStreamNonBlocking);
        cudaEventCreateWithFlags(&eFork, cudaEventDisableTiming);
        cudaEventCreateWithFlags(&e1, cudaEventDisableTiming);
        cudaEventCreateWithFlags(&e2, cudaEventDisableTiming);
    }

    constexpr int SMEM_BIG = 3 * (128 + 128) * 128;   // 98304
    constexpr int SMEM_SK  = 4 * (64 + 128) * 128;    // 98304
    cudaFuncSetAttribute(mm_f16_kernel<4, 4, 3, 0>, cudaFuncAttributeMaxDynamicSharedMemorySize, SMEM_BIG);
    cudaFuncSetAttribute(mm_f16_kernel<4, 4, 3, 1>, cudaFuncAttributeMaxDynamicSharedMemorySize, SMEM_BIG);
    cudaFuncSetAttribute(mm_f16_kernel<2, 4, 4, 0>, cudaFuncAttributeMaxDynamicSharedMemorySize, SMEM_SK);

    constexpr size_t BIG_CH = (size_t)HID * NR;
    constexpr size_t SK_CH  = (size_t)OUTD * NR;
    constexpr size_t NN = (size_t)NR * NR;

    // side stream: SEQUENTIAL conversions, dependency order.
    // Winv alone gets full DRAM bandwidth (~55us); W converts under uT GEMM.
    cudaEventRecord(eFork, 0);
    cudaStreamWaitEvent(s1, eFork, 0);
    cvt_f16_kernel<<<(int)(NN / (256 * 8)), 256, 0, s1>>>(Winv, Winvh, NN);
    cudaEventRecord(e1, s1);
    cvt_f16_kernel<<<(int)(NN / (256 * 8)), 256, 0, s1>>>(W, Wh, NN);
    cudaEventRecord(e2, s1);

    // main stream: small preps + tT GEMM (independent of W/Winv)
    cvt_f16_kernel<<<(NR * FIN) / (256 * 8), 256>>>(x, xh, (size_t)NR * FIN);
    transpose_h_kernel<<<dim3(HID / 32, FIN / 32), dim3(32, 8)>>>(w1, w1Th, FIN, HID);
    mm_f16_kernel<4, 4, 3, 1><<<dim3(NR / 128, HID / 128, 1), 256, SMEM_BIG>>>(
        w1Th, xh, tT, FIN, FIN, 0);

    // join Winvh, then uT (W conversion overlaps this GEMM)
    cudaStreamWaitEvent(0, e1, 0);
    mm_f16_kernel<4, 4, 3, 0><<<dim3(NR / 128, HID / 128, 2), 256, SMEM_BIG>>>(
        tT, Winvh, bp, NR, NR / 2, BIG_CH);
    combine_big_kernel<0><<<(int)(BIG_CH / 256), 256>>>(bp, f1, uT);

    // join Wh, then hT
    cudaStreamWaitEvent(0, e2, 0);
    mm_f16_kernel<4, 4, 3, 0><<<dim3(NR / 128, HID / 128, 2), 256, SMEM_BIG>>>(
        uT, Wh, bp, NR, NR / 2, BIG_CH);
    combine_big_kernel<1><<<(int)(BIG_CH / 256), 256>>>(bp, nullptr, hT);

    // layer 2
    gemm_small_kernel<<<NR / 128, 256>>>(w2, hT, sT);
    mm_f16_kernel<2, 4, 4, 0><<<dim3(NR / 128, 1, 4), 256, SMEM_SK>>>(
        sT, Winvh, part, NR, NR / 4, SK_CH);
    combine_vT_kernel<<<(int)(SK_CH / 256), 256>>>(part, f2, vT);
    mm_f16_kernel<2, 4, 4, 0><<<dim3(NR / 128, 1, 4), 256, SMEM_SK>>>(
        vT, Wh, part, NR, NR / 4, SK_CH);
    logsoftmax_part_kernel<<<NR / 256, 256>>>(part, out);
}